// round 5
// baseline (speedup 1.0000x reference)
#include <cuda_runtime.h>
#include <math.h>

#define NN   8192
#define DIMK 512

// Scratch (static __device__ — allocation-free per harness rules)
__device__ float g_n1[NN * DIMK];
__device__ float g_n2[NN * DIMK];
__device__ float g_S[(size_t)NN * NN];

// ---------------------------------------------------------------------------
// Bit-exact replica of XLA's f32 tanh as actually codegen'd (FMA-contracted
// Horner chains; separate roundings for x2, x*P and the division).
// ---------------------------------------------------------------------------
__device__ __forceinline__ float tanh_xla(float x)
{
    const float ax = fabsf(x);
    const float xc = fminf(fmaxf(x, -9.0f), 9.0f);
    const float x2 = __fmul_rn(xc, xc);

    float p = -2.76076847742355e-16f;
    p = __fmaf_rn(p, x2,  2.00018790482477e-13f);
    p = __fmaf_rn(p, x2, -8.60467152213735e-11f);
    p = __fmaf_rn(p, x2,  5.12229709037114e-08f);
    p = __fmaf_rn(p, x2,  1.48572235717979e-05f);
    p = __fmaf_rn(p, x2,  6.37261928875436e-04f);
    p = __fmaf_rn(p, x2,  4.89352455891786e-03f);
    const float num = __fmul_rn(xc, p);

    float q = 1.19825839466702e-06f;
    q = __fmaf_rn(q, x2, 1.18534705686654e-04f);
    q = __fmaf_rn(q, x2, 2.26843463243900e-03f);
    q = __fmaf_rn(q, x2, 4.89352518554385e-03f);

    const float r = __fdiv_rn(num, q);
    return (ax < 0.0004f) ? x : r;
}

// Packed f32x2 helpers: each half is an independent rn-rounded op, bitwise
// identical to the scalar fmaf — accumulation chains are unchanged per lane.
__device__ __forceinline__ unsigned long long bcast2(float a)
{
    unsigned long long d;
    const unsigned ai = __float_as_uint(a);
    asm("mov.b64 %0, {%1, %1};" : "=l"(d) : "r"(ai));
    return d;
}
__device__ __forceinline__ void fma2(unsigned long long& acc,
                                     unsigned long long a2,
                                     unsigned long long b2)
{
    asm("fma.rn.f32x2 %0, %1, %2, %3;" : "=l"(acc) : "l"(a2), "l"(b2), "l"(acc));
}

// ---------------------------------------------------------------------------
// SGEMM NT: C[M,N] = A[M,K] @ B[N,K]^T  (optionally +bias, tanh(3*(x+b)) epi,
// and row-gather of A through idx). k-sequential single-accumulator FMA chain
// per output element (bitwise-matches Eigen/cuBLAS accumulation order); the
// j-dimension is packed 2-wide into fma.rn.f32x2 (FFMA2) for 2x FMA tput.
// 128x128x16 tiles, 256 threads, 8x8 per thread, double-buffered smem.
// ---------------------------------------------------------------------------
template<bool GATHER, bool TANH_EPI>
__global__ void __launch_bounds__(256, 2)
sgemm_nt(const float* __restrict__ A, const float* __restrict__ B,
         const float* __restrict__ bias, const int* __restrict__ idx,
         float* __restrict__ C, int M, int N, int K)
{
    constexpr int BM = 128, BN = 128, BK = 16;
    __shared__ float As[2][BK][BM + 4];
    __shared__ float Bs[2][BK][BN + 4];

    const int tid = threadIdx.x;
    const int bx = blockIdx.x, by = blockIdx.y;

    const int lr = tid >> 2;          // 0..63
    const int lc = (tid & 3) << 2;    // 0,4,8,12

    int ar0 = by * BM + lr;
    int ar1 = ar0 + 64;
    if (GATHER) { ar0 = idx[ar0]; ar1 = idx[ar1]; }
    const float* Ap0 = A + (size_t)ar0 * K + lc;
    const float* Ap1 = A + (size_t)ar1 * K + lc;
    const float* Bp0 = B + (size_t)(bx * BN + lr) * K + lc;
    const float* Bp1 = B + (size_t)(bx * BN + lr + 64) * K + lc;

    const int rm = (tid >> 4) << 3;   // 0..120
    const int rn = (tid & 15) << 3;   // 0..120

    // acc2[i][j] holds output columns (rn+2j, rn+2j+1) for row rm+i
    unsigned long long acc2[8][4];
    #pragma unroll
    for (int i = 0; i < 8; ++i)
        #pragma unroll
        for (int j = 0; j < 4; ++j) acc2[i][j] = 0ull;

    float4 pa0, pa1, pb0, pb1;

    pa0 = *reinterpret_cast<const float4*>(Ap0);
    pa1 = *reinterpret_cast<const float4*>(Ap1);
    pb0 = *reinterpret_cast<const float4*>(Bp0);
    pb1 = *reinterpret_cast<const float4*>(Bp1);
    {
        As[0][lc + 0][lr] = pa0.x; As[0][lc + 1][lr] = pa0.y;
        As[0][lc + 2][lr] = pa0.z; As[0][lc + 3][lr] = pa0.w;
        As[0][lc + 0][lr + 64] = pa1.x; As[0][lc + 1][lr + 64] = pa1.y;
        As[0][lc + 2][lr + 64] = pa1.z; As[0][lc + 3][lr + 64] = pa1.w;
        Bs[0][lc + 0][lr] = pb0.x; Bs[0][lc + 1][lr] = pb0.y;
        Bs[0][lc + 2][lr] = pb0.z; Bs[0][lc + 3][lr] = pb0.w;
        Bs[0][lc + 0][lr + 64] = pb1.x; Bs[0][lc + 1][lr + 64] = pb1.y;
        Bs[0][lc + 2][lr + 64] = pb1.z; Bs[0][lc + 3][lr + 64] = pb1.w;
    }
    __syncthreads();

    int read = 0;
    for (int kt = BK; kt <= K; kt += BK) {
        const bool more = (kt < K);
        if (more) {
            pa0 = *reinterpret_cast<const float4*>(Ap0 + kt);
            pa1 = *reinterpret_cast<const float4*>(Ap1 + kt);
            pb0 = *reinterpret_cast<const float4*>(Bp0 + kt);
            pb1 = *reinterpret_cast<const float4*>(Bp1 + kt);
        }
        #pragma unroll
        for (int kk = 0; kk < BK; ++kk) {
            float ra[8];
            unsigned long long rb2[4];
            *reinterpret_cast<float4*>(&ra[0]) = *reinterpret_cast<const float4*>(&As[read][kk][rm]);
            *reinterpret_cast<float4*>(&ra[4]) = *reinterpret_cast<const float4*>(&As[read][kk][rm + 4]);
            // Bs row stride is (BN+4)*4 = 528 B (16-aligned) and rn*4 is
            // 32-aligned, so these 128-bit loads are aligned; lo/hi halves of
            // each u64 are consecutive columns (j, j+1).
            *reinterpret_cast<float4*>(&rb2[0]) = *reinterpret_cast<const float4*>(&Bs[read][kk][rn]);
            *reinterpret_cast<float4*>(&rb2[2]) = *reinterpret_cast<const float4*>(&Bs[read][kk][rn + 4]);

            #pragma unroll
            for (int i = 0; i < 8; ++i) {
                const unsigned long long a2 = bcast2(ra[i]);
                #pragma unroll
                for (int j = 0; j < 4; ++j)
                    fma2(acc2[i][j], a2, rb2[j]);
            }
        }
        if (more) {
            const int w = read ^ 1;
            As[w][lc + 0][lr] = pa0.x; As[w][lc + 1][lr] = pa0.y;
            As[w][lc + 2][lr] = pa0.z; As[w][lc + 3][lr] = pa0.w;
            As[w][lc + 0][lr + 64] = pa1.x; As[w][lc + 1][lr + 64] = pa1.y;
            As[w][lc + 2][lr + 64] = pa1.z; As[w][lc + 3][lr + 64] = pa1.w;
            Bs[w][lc + 0][lr] = pb0.x; Bs[w][lc + 1][lr] = pb0.y;
            Bs[w][lc + 2][lr] = pb0.z; Bs[w][lc + 3][lr] = pb0.w;
            Bs[w][lc + 0][lr + 64] = pb1.x; Bs[w][lc + 1][lr + 64] = pb1.y;
            Bs[w][lc + 2][lr + 64] = pb1.z; Bs[w][lc + 3][lr + 64] = pb1.w;
            __syncthreads();
            read = w;
        }
    }

    #pragma unroll
    for (int i = 0; i < 8; ++i) {
        const size_t row = (size_t)(by * BM + rm + i);
        float v[8];
        #pragma unroll
        for (int j = 0; j < 4; ++j) {
            const float2 u = *reinterpret_cast<const float2*>(&acc2[i][j]);
            v[2 * j]     = u.x;
            v[2 * j + 1] = u.y;
        }
        if constexpr (TANH_EPI) {
            #pragma unroll
            for (int j = 0; j < 8; ++j) {
                float x = __fadd_rn(v[j], bias[bx * BN + rn + j]);
                x = __fmul_rn(3.0f, x);
                v[j] = tanh_xla(x);
            }
        }
        float4* cp = reinterpret_cast<float4*>(C + row * (size_t)N + bx * BN + rn);
        cp[0] = make_float4(v[0], v[1], v[2], v[3]);
        cp[1] = make_float4(v[4], v[5], v[6], v[7]);
    }
}

// ---------------------------------------------------------------------------
// In-place antisymmetrize + tanh: adj = tanh(3*(S - S^T)), tile-pair per CTA.
// 512 threads, 8 rows each (lower regs/thread -> higher occupancy than R4).
// ---------------------------------------------------------------------------
__global__ void __launch_bounds__(512)
antisym_tanh(float* __restrict__ S, int N)
{
    const int I = blockIdx.y, J = blockIdx.x;
    if (J < I) return;

    __shared__ float t1[64][65];
    __shared__ float t2[64][65];

    const int c  = threadIdx.x & 63;
    const int r0 = (threadIdx.x >> 6) << 3;   // 0,8,...,56

    const size_t base1 = (size_t)(I * 64) * N + (size_t)(J * 64);
    const size_t base2 = (size_t)(J * 64) * N + (size_t)(I * 64);

    #pragma unroll
    for (int e = 0; e < 8; ++e) {
        const int r = r0 + e;
        t1[r][c] = S[base1 + (size_t)r * N + c];
        t2[r][c] = S[base2 + (size_t)r * N + c];
    }
    __syncthreads();

    float v[8];
    #pragma unroll
    for (int e = 0; e < 8; ++e) {
        const int r = r0 + e;
        const float a = __fadd_rn(t1[r][c], -t2[c][r]);
        v[e] = tanh_xla(__fmul_rn(3.0f, a));
    }
    __syncthreads();

    #pragma unroll
    for (int e = 0; e < 8; ++e) {
        const int r = r0 + e;
        S[base1 + (size_t)r * N + c] = v[e];
        t2[c][r] = -v[e];                       // tanh odd; antisymmetry exact
    }
    __syncthreads();

    if (I != J) {
        #pragma unroll
        for (int e = 0; e < 8; ++e) {
            const int r = r0 + e;
            S[base2 + (size_t)r * N + c] = t2[r][c];
        }
    }
}

// ---------------------------------------------------------------------------
// Per-row exact top-k mask with jax.lax.top_k tie semantics:
//   pang = |fma(0.01, noise, adj)|   (XLA contracts mul+add -> FMA)
//   T = k-th largest (exact MSB radix-select on uint bits); keep all > T plus
//   lowest-index == T entries until exactly k kept.
// ---------------------------------------------------------------------------
#define EQ_CAP 256

__global__ void __launch_bounds__(256)
topk_mask(const float* __restrict__ adj, const float* __restrict__ noise,
          const int* __restrict__ kptr, float* __restrict__ out, int N, int kdef)
{
    __shared__ float sadj[NN];
    __shared__ int cnt[32];
    __shared__ int eq_idx[EQ_CAP];
    __shared__ int eq_n;
    __shared__ int gt_n;

    const int row = blockIdx.x;
    const int tid = threadIdx.x;
    const float* ar = adj   + (size_t)row * N;
    const float* nr = noise + (size_t)row * N;

    unsigned pbits[32];
    #pragma unroll
    for (int e = 0; e < 32; ++e) {
        const int j = tid + (e << 8);
        const float a = ar[j];
        const float p = fabsf(__fmaf_rn(0.01f, nr[j], a));
        sadj[j]  = a;
        pbits[e] = __float_as_uint(p);
    }
    if (tid < 32) cnt[tid] = 0;
    if (tid == 0) { eq_n = 0; gt_n = 0; }
    __syncthreads();

    const int k = kptr ? *kptr : kdef;
    unsigned prefix = 0;
    int kk = k;
    for (int b = 30; b >= 0; --b) {
        const unsigned cand = prefix | (1u << b);
        const unsigned hm   = ~((1u << b) - 1u);
        int c = 0;
        #pragma unroll
        for (int e = 0; e < 32; ++e) c += ((pbits[e] & hm) == cand);
        #pragma unroll
        for (int o = 16; o > 0; o >>= 1) c += __shfl_xor_sync(0xffffffffu, c, o);
        if ((tid & 31) == 0) atomicAdd(&cnt[b], c);
        __syncthreads();
        const int tot = cnt[b];
        if (tot >= kk) prefix = cand; else kk -= tot;
    }

    const unsigned T = prefix;

    {
        int cgt = 0;
        #pragma unroll
        for (int e = 0; e < 32; ++e) cgt += (pbits[e] > T);
        #pragma unroll
        for (int o = 16; o > 0; o >>= 1) cgt += __shfl_xor_sync(0xffffffffu, cgt, o);
        if ((tid & 31) == 0) atomicAdd(&gt_n, cgt);

        #pragma unroll
        for (int e = 0; e < 32; ++e) {
            if (pbits[e] == T) {
                const int s = atomicAdd(&eq_n, 1);
                if (s < EQ_CAP) eq_idx[s] = tid + (e << 8);
            }
        }
    }
    __syncthreads();

    const int need = k - gt_n;
    const int en   = (eq_n < EQ_CAP) ? eq_n : EQ_CAP;

    #pragma unroll
    for (int e = 0; e < 32; ++e) {
        const int j = tid + (e << 8);
        bool keep = (pbits[e] > T);
        if (!keep && pbits[e] == T) {
            int r = 0;
            for (int q = 0; q < en; ++q) r += (eq_idx[q] < j);
            keep = (r < need);
        }
        out[(size_t)row * N + j] = keep ? sadj[j] : 0.0f;
    }
}

// ---------------------------------------------------------------------------
// Launcher: inputs in metadata order:
// idx, emb1, emb2, lin1_w, lin1_b, lin2_w, lin2_b, noise, k
// ---------------------------------------------------------------------------
extern "C" void kernel_launch(void* const* d_in, const int* in_sizes, int n_in,
                              void* d_out, int out_size)
{
    const int*   idx   = (const int*)  d_in[0];
    const float* emb1  = (const float*)d_in[1];
    const float* emb2  = (const float*)d_in[2];
    const float* w1    = (const float*)d_in[3];
    const float* b1    = (const float*)d_in[4];
    const float* w2    = (const float*)d_in[5];
    const float* b2    = (const float*)d_in[6];
    const float* noise = (const float*)d_in[7];
    const int*   kptr  = (n_in > 8) ? (const int*)d_in[8] : nullptr;
    float* out = (float*)d_out;

    float *n1, *n2, *S;
    cudaGetSymbolAddress((void**)&n1, g_n1);
    cudaGetSymbolAddress((void**)&n2, g_n2);
    cudaGetSymbolAddress((void**)&S,  g_S);

    // Phase 1: n1/n2 = tanh(3*(emb[idx] @ W^T + b))   [8192 x 512]
    {
        dim3 grid(DIMK / 128, NN / 128);
        sgemm_nt<true, true><<<grid, 256>>>(emb1, w1, b1, idx, n1, NN, DIMK, DIMK);
        sgemm_nt<true, true><<<grid, 256>>>(emb2, w2, b2, idx, n2, NN, DIMK, DIMK);
    }

    // Phase 2: S = n1 @ n2^T   [8192 x 8192]
    {
        dim3 grid(NN / 128, NN / 128);
        sgemm_nt<false, false><<<grid, 256>>>(n1, n2, nullptr, nullptr, S, NN, NN, DIMK);
    }

    // Phase 3: adj = tanh(3*(S - S^T)) in place (tile pairs)
    {
        dim3 grid(NN / 64, NN / 64);
        antisym_tanh<<<grid, 512>>>(S, NN);
    }

    // Phase 4: per-row exact top-k mask (jax tie semantics) -> output
    topk_mask<<<NN, 256>>>(S, noise, kptr, out, NN, 64);
}

// round 6
// speedup vs baseline: 1.0762x; 1.0762x over previous
#include <cuda_runtime.h>
#include <math.h>

#define NN   8192
#define DIMK 512

// Scratch (static __device__ — allocation-free per harness rules)
__device__ float g_n1[NN * DIMK];
__device__ float g_n2[NN * DIMK];
__device__ float g_S[(size_t)NN * NN];

// ---------------------------------------------------------------------------
// Bit-exact replica of XLA's f32 tanh as actually codegen'd (FMA-contracted
// Horner chains; separate roundings for x2, x*P and the division).
// ---------------------------------------------------------------------------
__device__ __forceinline__ float tanh_xla(float x)
{
    const float ax = fabsf(x);
    const float xc = fminf(fmaxf(x, -9.0f), 9.0f);
    const float x2 = __fmul_rn(xc, xc);

    float p = -2.76076847742355e-16f;
    p = __fmaf_rn(p, x2,  2.00018790482477e-13f);
    p = __fmaf_rn(p, x2, -8.60467152213735e-11f);
    p = __fmaf_rn(p, x2,  5.12229709037114e-08f);
    p = __fmaf_rn(p, x2,  1.48572235717979e-05f);
    p = __fmaf_rn(p, x2,  6.37261928875436e-04f);
    p = __fmaf_rn(p, x2,  4.89352455891786e-03f);
    const float num = __fmul_rn(xc, p);

    float q = 1.19825839466702e-06f;
    q = __fmaf_rn(q, x2, 1.18534705686654e-04f);
    q = __fmaf_rn(q, x2, 2.26843463243900e-03f);
    q = __fmaf_rn(q, x2, 4.89352518554385e-03f);

    const float r = __fdiv_rn(num, q);
    return (ax < 0.0004f) ? x : r;
}

// packed f32x2 FMA: each half is an independent rn-rounded FMA (bitwise equal
// to scalar fmaf); accumulate in place.
__device__ __forceinline__ void fma2(unsigned long long& acc,
                                     unsigned long long a2,
                                     unsigned long long b2)
{
    asm("fma.rn.f32x2 %0, %1, %2, %0;" : "+l"(acc) : "l"(a2), "l"(b2));
}

// ---------------------------------------------------------------------------
// PHASE-1 testbed: SGEMM NT with f32x2 accumulation (FFMA2 experiment).
// C = tanh(3*(A[idx] @ B^T + bias)), M=8192, N=K=512.
// A-operand pre-duplicated in smem as (a,a) float2 pairs: fragment loads give
// ready-made 64-bit broadcast lanes — no per-iteration packing movs.
// 128x128x16 tiles, 256 threads, 8 rows x 4 col-pairs per thread.
// smem = exactly 48KB (As2 32KB + Bs 16KB), no launch_bounds min-blocks.
// ---------------------------------------------------------------------------
__global__ void __launch_bounds__(256)
sgemm_nt_x2_epi(const float* __restrict__ A, const float* __restrict__ B,
                const float* __restrict__ bias, const int* __restrict__ idx,
                float* __restrict__ C, int M, int N, int K)
{
    constexpr int BM = 128, BN = 128, BK = 16;
    __shared__ float2 As2[2][BK][BM];      // duplicated pairs (a,a)
    __shared__ float  Bs [2][BK][BN];      // natural col pairs

    const int tid = threadIdx.x;
    const int bx = blockIdx.x, by = blockIdx.y;

    const int lr = tid >> 2;          // 0..63
    const int lc = (tid & 3) << 2;    // 0,4,8,12

    int ar0 = idx[by * BM + lr];
    int ar1 = idx[by * BM + lr + 64];
    const float* Ap0 = A + (size_t)ar0 * K + lc;
    const float* Ap1 = A + (size_t)ar1 * K + lc;
    const float* Bp0 = B + (size_t)(bx * BN + lr) * K + lc;
    const float* Bp1 = B + (size_t)(bx * BN + lr + 64) * K + lc;

    const int rm = (tid >> 4) << 3;   // 0..120
    const int rn = (tid & 15) << 3;   // 0..120

    unsigned long long acc2[8][4];
    #pragma unroll
    for (int i = 0; i < 8; ++i)
        #pragma unroll
        for (int j = 0; j < 4; ++j) acc2[i][j] = 0ull;

    float4 pa0, pa1, pb0, pb1;

    pa0 = *reinterpret_cast<const float4*>(Ap0);
    pa1 = *reinterpret_cast<const float4*>(Ap1);
    pb0 = *reinterpret_cast<const float4*>(Bp0);
    pb1 = *reinterpret_cast<const float4*>(Bp1);
    {
        As2[0][lc + 0][lr] = make_float2(pa0.x, pa0.x);
        As2[0][lc + 1][lr] = make_float2(pa0.y, pa0.y);
        As2[0][lc + 2][lr] = make_float2(pa0.z, pa0.z);
        As2[0][lc + 3][lr] = make_float2(pa0.w, pa0.w);
        As2[0][lc + 0][lr + 64] = make_float2(pa1.x, pa1.x);
        As2[0][lc + 1][lr + 64] = make_float2(pa1.y, pa1.y);
        As2[0][lc + 2][lr + 64] = make_float2(pa1.z, pa1.z);
        As2[0][lc + 3][lr + 64] = make_float2(pa1.w, pa1.w);
        Bs[0][lc + 0][lr] = pb0.x; Bs[0][lc + 1][lr] = pb0.y;
        Bs[0][lc + 2][lr] = pb0.z; Bs[0][lc + 3][lr] = pb0.w;
        Bs[0][lc + 0][lr + 64] = pb1.x; Bs[0][lc + 1][lr + 64] = pb1.y;
        Bs[0][lc + 2][lr + 64] = pb1.z; Bs[0][lc + 3][lr + 64] = pb1.w;
    }
    __syncthreads();

    int read = 0;
    for (int kt = BK; kt <= K; kt += BK) {
        const bool more = (kt < K);
        if (more) {
            pa0 = *reinterpret_cast<const float4*>(Ap0 + kt);
            pa1 = *reinterpret_cast<const float4*>(Ap1 + kt);
            pb0 = *reinterpret_cast<const float4*>(Bp0 + kt);
            pb1 = *reinterpret_cast<const float4*>(Bp1 + kt);
        }
        #pragma unroll
        for (int kk = 0; kk < BK; ++kk) {
            unsigned long long ra2[8], rb2[4];
            // As2 row: 8 duplicated pairs = 64B, rm*8B is 64B-aligned
            *reinterpret_cast<float4*>(&ra2[0]) = *reinterpret_cast<const float4*>(&As2[read][kk][rm]);
            *reinterpret_cast<float4*>(&ra2[2]) = *reinterpret_cast<const float4*>(&As2[read][kk][rm + 2]);
            *reinterpret_cast<float4*>(&ra2[4]) = *reinterpret_cast<const float4*>(&As2[read][kk][rm + 4]);
            *reinterpret_cast<float4*>(&ra2[6]) = *reinterpret_cast<const float4*>(&As2[read][kk][rm + 6]);
            // Bs row: natural (j, j+1) pairs, rn*4B is 32B-aligned
            *reinterpret_cast<float4*>(&rb2[0]) = *reinterpret_cast<const float4*>(&Bs[read][kk][rn]);
            *reinterpret_cast<float4*>(&rb2[2]) = *reinterpret_cast<const float4*>(&Bs[read][kk][rn + 4]);

            #pragma unroll
            for (int i = 0; i < 8; ++i)
                #pragma unroll
                for (int j = 0; j < 4; ++j)
                    fma2(acc2[i][j], ra2[i], rb2[j]);
        }
        if (more) {
            const int w = read ^ 1;
            As2[w][lc + 0][lr] = make_float2(pa0.x, pa0.x);
            As2[w][lc + 1][lr] = make_float2(pa0.y, pa0.y);
            As2[w][lc + 2][lr] = make_float2(pa0.z, pa0.z);
            As2[w][lc + 3][lr] = make_float2(pa0.w, pa0.w);
            As2[w][lc + 0][lr + 64] = make_float2(pa1.x, pa1.x);
            As2[w][lc + 1][lr + 64] = make_float2(pa1.y, pa1.y);
            As2[w][lc + 2][lr + 64] = make_float2(pa1.z, pa1.z);
            As2[w][lc + 3][lr + 64] = make_float2(pa1.w, pa1.w);
            Bs[w][lc + 0][lr] = pb0.x; Bs[w][lc + 1][lr] = pb0.y;
            Bs[w][lc + 2][lr] = pb0.z; Bs[w][lc + 3][lr] = pb0.w;
            Bs[w][lc + 0][lr + 64] = pb1.x; Bs[w][lc + 1][lr + 64] = pb1.y;
            Bs[w][lc + 2][lr + 64] = pb1.z; Bs[w][lc + 3][lr + 64] = pb1.w;
            __syncthreads();
            read = w;
        }
    }

    #pragma unroll
    for (int i = 0; i < 8; ++i) {
        const size_t row = (size_t)(by * BM + rm + i);
        float v[8];
        #pragma unroll
        for (int j = 0; j < 4; ++j) {
            const float2 u = *reinterpret_cast<const float2*>(&acc2[i][j]);
            v[2 * j]     = u.x;
            v[2 * j + 1] = u.y;
        }
        #pragma unroll
        for (int j = 0; j < 8; ++j) {
            float x = __fadd_rn(v[j], bias[bx * BN + rn + j]);
            x = __fmul_rn(3.0f, x);
            v[j] = tanh_xla(x);
        }
        float4* cp = reinterpret_cast<float4*>(C + row * (size_t)N + bx * BN + rn);
        cp[0] = make_float4(v[0], v[1], v[2], v[3]);
        cp[1] = make_float4(v[4], v[5], v[6], v[7]);
    }
}

// ---------------------------------------------------------------------------
// PHASE-2: known-good scalar SGEMM NT (exact R4 code path, 1860us measured).
// C[M,N] = A[M,K] @ B[N,K]^T, k-sequential single-accumulator FMA chain.
// ---------------------------------------------------------------------------
__global__ void __launch_bounds__(256, 2)
sgemm_nt_scalar(const float* __restrict__ A, const float* __restrict__ B,
                float* __restrict__ C, int M, int N, int K)
{
    constexpr int BM = 128, BN = 128, BK = 16;
    __shared__ float As[2][BK][BM + 4];
    __shared__ float Bs[2][BK][BN + 4];

    const int tid = threadIdx.x;
    const int bx = blockIdx.x, by = blockIdx.y;

    const int lr = tid >> 2;
    const int lc = (tid & 3) << 2;

    const float* Ap0 = A + (size_t)(by * BM + lr) * K + lc;
    const float* Ap1 = A + (size_t)(by * BM + lr + 64) * K + lc;
    const float* Bp0 = B + (size_t)(bx * BN + lr) * K + lc;
    const float* Bp1 = B + (size_t)(bx * BN + lr + 64) * K + lc;

    const int rm = (tid >> 4) << 3;
    const int rn = (tid & 15) << 3;

    float acc[8][8];
    #pragma unroll
    for (int i = 0; i < 8; ++i)
        #pragma unroll
        for (int j = 0; j < 8; ++j) acc[i][j] = 0.0f;

    float4 pa0, pa1, pb0, pb1;

    pa0 = *reinterpret_cast<const float4*>(Ap0);
    pa1 = *reinterpret_cast<const float4*>(Ap1);
    pb0 = *reinterpret_cast<const float4*>(Bp0);
    pb1 = *reinterpret_cast<const float4*>(Bp1);
    {
        As[0][lc + 0][lr] = pa0.x; As[0][lc + 1][lr] = pa0.y;
        As[0][lc + 2][lr] = pa0.z; As[0][lc + 3][lr] = pa0.w;
        As[0][lc + 0][lr + 64] = pa1.x; As[0][lc + 1][lr + 64] = pa1.y;
        As[0][lc + 2][lr + 64] = pa1.z; As[0][lc + 3][lr + 64] = pa1.w;
        Bs[0][lc + 0][lr] = pb0.x; Bs[0][lc + 1][lr] = pb0.y;
        Bs[0][lc + 2][lr] = pb0.z; Bs[0][lc + 3][lr] = pb0.w;
        Bs[0][lc + 0][lr + 64] = pb1.x; Bs[0][lc + 1][lr + 64] = pb1.y;
        Bs[0][lc + 2][lr + 64] = pb1.z; Bs[0][lc + 3][lr + 64] = pb1.w;
    }
    __syncthreads();

    int read = 0;
    for (int kt = BK; kt <= K; kt += BK) {
        const bool more = (kt < K);
        if (more) {
            pa0 = *reinterpret_cast<const float4*>(Ap0 + kt);
            pa1 = *reinterpret_cast<const float4*>(Ap1 + kt);
            pb0 = *reinterpret_cast<const float4*>(Bp0 + kt);
            pb1 = *reinterpret_cast<const float4*>(Bp1 + kt);
        }
        #pragma unroll
        for (int kk = 0; kk < BK; ++kk) {
            float ra[8], rb[8];
            *reinterpret_cast<float4*>(&ra[0]) = *reinterpret_cast<const float4*>(&As[read][kk][rm]);
            *reinterpret_cast<float4*>(&ra[4]) = *reinterpret_cast<const float4*>(&As[read][kk][rm + 4]);
            *reinterpret_cast<float4*>(&rb[0]) = *reinterpret_cast<const float4*>(&Bs[read][kk][rn]);
            *reinterpret_cast<float4*>(&rb[4]) = *reinterpret_cast<const float4*>(&Bs[read][kk][rn + 4]);
            #pragma unroll
            for (int i = 0; i < 8; ++i)
                #pragma unroll
                for (int j = 0; j < 8; ++j)
                    acc[i][j] = fmaf(ra[i], rb[j], acc[i][j]);
        }
        if (more) {
            const int w = read ^ 1;
            As[w][lc + 0][lr] = pa0.x; As[w][lc + 1][lr] = pa0.y;
            As[w][lc + 2][lr] = pa0.z; As[w][lc + 3][lr] = pa0.w;
            As[w][lc + 0][lr + 64] = pa1.x; As[w][lc + 1][lr + 64] = pa1.y;
            As[w][lc + 2][lr + 64] = pa1.z; As[w][lc + 3][lr + 64] = pa1.w;
            Bs[w][lc + 0][lr] = pb0.x; Bs[w][lc + 1][lr] = pb0.y;
            Bs[w][lc + 2][lr] = pb0.z; Bs[w][lc + 3][lr] = pb0.w;
            Bs[w][lc + 0][lr + 64] = pb1.x; Bs[w][lc + 1][lr + 64] = pb1.y;
            Bs[w][lc + 2][lr + 64] = pb1.z; Bs[w][lc + 3][lr + 64] = pb1.w;
            __syncthreads();
            read = w;
        }
    }

    #pragma unroll
    for (int i = 0; i < 8; ++i) {
        const size_t row = (size_t)(by * BM + rm + i);
        float4* cp = reinterpret_cast<float4*>(C + row * (size_t)N + bx * BN + rn);
        cp[0] = make_float4(acc[i][0], acc[i][1], acc[i][2], acc[i][3]);
        cp[1] = make_float4(acc[i][4], acc[i][5], acc[i][6], acc[i][7]);
    }
}

// ---------------------------------------------------------------------------
// In-place antisymmetrize + tanh: adj = tanh(3*(S - S^T)), tile-pair per CTA.
// 512 threads, 8 rows each (R5-measured: 122us).
// ---------------------------------------------------------------------------
__global__ void __launch_bounds__(512)
antisym_tanh(float* __restrict__ S, int N)
{
    const int I = blockIdx.y, J = blockIdx.x;
    if (J < I) return;

    __shared__ float t1[64][65];
    __shared__ float t2[64][65];

    const int c  = threadIdx.x & 63;
    const int r0 = (threadIdx.x >> 6) << 3;

    const size_t base1 = (size_t)(I * 64) * N + (size_t)(J * 64);
    const size_t base2 = (size_t)(J * 64) * N + (size_t)(I * 64);

    #pragma unroll
    for (int e = 0; e < 8; ++e) {
        const int r = r0 + e;
        t1[r][c] = S[base1 + (size_t)r * N + c];
        t2[r][c] = S[base2 + (size_t)r * N + c];
    }
    __syncthreads();

    float v[8];
    #pragma unroll
    for (int e = 0; e < 8; ++e) {
        const int r = r0 + e;
        const float a = __fadd_rn(t1[r][c], -t2[c][r]);
        v[e] = tanh_xla(__fmul_rn(3.0f, a));
    }
    __syncthreads();

    #pragma unroll
    for (int e = 0; e < 8; ++e) {
        const int r = r0 + e;
        S[base1 + (size_t)r * N + c] = v[e];
        t2[c][r] = -v[e];
    }
    __syncthreads();

    if (I != J) {
        #pragma unroll
        for (int e = 0; e < 8; ++e) {
            const int r = r0 + e;
            S[base2 + (size_t)r * N + c] = t2[r][c];
        }
    }
}

// ---------------------------------------------------------------------------
// Per-row exact top-k mask with jax.lax.top_k tie semantics.
// ---------------------------------------------------------------------------
#define EQ_CAP 256

__global__ void __launch_bounds__(256)
topk_mask(const float* __restrict__ adj, const float* __restrict__ noise,
          const int* __restrict__ kptr, float* __restrict__ out, int N, int kdef)
{
    __shared__ float sadj[NN];
    __shared__ int cnt[32];
    __shared__ int eq_idx[EQ_CAP];
    __shared__ int eq_n;
    __shared__ int gt_n;

    const int row = blockIdx.x;
    const int tid = threadIdx.x;
    const float* ar = adj   + (size_t)row * N;
    const float* nr = noise + (size_t)row * N;

    unsigned pbits[32];
    #pragma unroll
    for (int e = 0; e < 32; ++e) {
        const int j = tid + (e << 8);
        const float a = ar[j];
        const float p = fabsf(__fmaf_rn(0.01f, nr[j], a));
        sadj[j]  = a;
        pbits[e] = __float_as_uint(p);
    }
    if (tid < 32) cnt[tid] = 0;
    if (tid == 0) { eq_n = 0; gt_n = 0; }
    __syncthreads();

    const int k = kptr ? *kptr : kdef;
    unsigned prefix = 0;
    int kk = k;
    for (int b = 30; b >= 0; --b) {
        const unsigned cand = prefix | (1u << b);
        const unsigned hm   = ~((1u << b) - 1u);
        int c = 0;
        #pragma unroll
        for (int e = 0; e < 32; ++e) c += ((pbits[e] & hm) == cand);
        #pragma unroll
        for (int o = 16; o > 0; o >>= 1) c += __shfl_xor_sync(0xffffffffu, c, o);
        if ((tid & 31) == 0) atomicAdd(&cnt[b], c);
        __syncthreads();
        const int tot = cnt[b];
        if (tot >= kk) prefix = cand; else kk -= tot;
    }

    const unsigned T = prefix;

    {
        int cgt = 0;
        #pragma unroll
        for (int e = 0; e < 32; ++e) cgt += (pbits[e] > T);
        #pragma unroll
        for (int o = 16; o > 0; o >>= 1) cgt += __shfl_xor_sync(0xffffffffu, cgt, o);
        if ((tid & 31) == 0) atomicAdd(&gt_n, cgt);

        #pragma unroll
        for (int e = 0; e < 32; ++e) {
            if (pbits[e] == T) {
                const int s = atomicAdd(&eq_n, 1);
                if (s < EQ_CAP) eq_idx[s] = tid + (e << 8);
            }
        }
    }
    __syncthreads();

    const int need = k - gt_n;
    const int en   = (eq_n < EQ_CAP) ? eq_n : EQ_CAP;

    #pragma unroll
    for (int e = 0; e < 32; ++e) {
        const int j = tid + (e << 8);
        bool keep = (pbits[e] > T);
        if (!keep && pbits[e] == T) {
            int r = 0;
            for (int q = 0; q < en; ++q) r += (eq_idx[q] < j);
            keep = (r < need);
        }
        out[(size_t)row * N + j] = keep ? sadj[j] : 0.0f;
    }
}

// ---------------------------------------------------------------------------
// Launcher: inputs in metadata order:
// idx, emb1, emb2, lin1_w, lin1_b, lin2_w, lin2_b, noise, k
// ---------------------------------------------------------------------------
extern "C" void kernel_launch(void* const* d_in, const int* in_sizes, int n_in,
                              void* d_out, int out_size)
{
    const int*   idx   = (const int*)  d_in[0];
    const float* emb1  = (const float*)d_in[1];
    const float* emb2  = (const float*)d_in[2];
    const float* w1    = (const float*)d_in[3];
    const float* b1    = (const float*)d_in[4];
    const float* w2    = (const float*)d_in[5];
    const float* b2    = (const float*)d_in[6];
    const float* noise = (const float*)d_in[7];
    const int*   kptr  = (n_in > 8) ? (const int*)d_in[8] : nullptr;
    float* out = (float*)d_out;

    float *n1, *n2, *S;
    cudaGetSymbolAddress((void**)&n1, g_n1);
    cudaGetSymbolAddress((void**)&n2, g_n2);
    cudaGetSymbolAddress((void**)&S,  g_S);

    // Phase 1 (FFMA2 testbed): n1/n2 = tanh(3*(emb[idx] @ W^T + b))
    {
        dim3 grid(DIMK / 128, NN / 128);
        sgemm_nt_x2_epi<<<grid, 256>>>(emb1, w1, b1, idx, n1, NN, DIMK, DIMK);
        sgemm_nt_x2_epi<<<grid, 256>>>(emb2, w2, b2, idx, n2, NN, DIMK, DIMK);
    }

    // Phase 2 (known-good scalar): S = n1 @ n2^T
    {
        dim3 grid(NN / 128, NN / 128);
        sgemm_nt_scalar<<<grid, 256>>>(n1, n2, S, NN, NN, DIMK);
    }

    // Phase 3: adj = tanh(3*(S - S^T)) in place (tile pairs)
    {
        dim3 grid(NN / 64, NN / 64);
        antisym_tanh<<<grid, 512>>>(S, NN);
    }

    // Phase 4: per-row exact top-k mask (jax tie semantics) -> output
    topk_mask<<<NN, 256>>>(S, noise, kptr, out, NN, 64);
}